// round 13
// baseline (speedup 1.0000x reference)
#include <cuda_runtime.h>
#include <cuda_fp16.h>
#include <math_constants.h>

#define NGRAPHS 2048
#define NUMK    128
#define NE      1024
#define NE_PAD  1408            // NE + up to 3 pad slots per node (segments %4 == 0)
#define HD      32
#define ROWLEN  (NUMK + NE + 2)

// Built once per launch (edge template + weights identical across graphs).
// All node ids below are DEGREE-SORTED RANKS. CSR segments padded to %4 length.
__device__ int g_einfo[NE];                     // per edge id: csr_pos | src_rank<<11 | dst_rank<<18
__device__ int g_ptr[NUMK + 1];                 // padded CSR ptr over dst ranks (all %4)
__device__ int g_rank[NUMK];                    // original node -> rank
__device__ float g_t[HD];                       // relu thresholds t_k = -b1k/W1k
__device__ __align__(16) float g_A[33 * HD];    // h = s1*A[iv] + C[iv]
__device__ __align__(16) float g_C[33 * HD];

// ---- single prep launch: block 0 = rank+CSR build; blocks 1..33 = tables ----
__global__ __launch_bounds__(256) void gcn_prep(const int* __restrict__ ew,
                                                const float* __restrict__ W1,
                                                const float* __restrict__ b1,
                                                const float* __restrict__ W2) {
    if (blockIdx.x == 0) {
        __shared__ unsigned char src_sh[NE], dst_sh[NE];
        __shared__ int cnt[NUMK];
        __shared__ int rank_sh[NUMK];
        __shared__ int cntr[NUMK];
        __shared__ int base_sh[NUMK + 1];
        __shared__ int wsum[4];
        __shared__ int odd_nonzero;
        const int t = threadIdx.x;
        if (t == 0) odd_nonzero = 0;
        if (t < NUMK) cnt[t] = 0;
        __syncthreads();
        // int32 vs int64 layout guard: odd words all-zero => little-endian int64
        int nz = 0;
        for (int i = t * 2 + 1; i < 2 * NE; i += 512) nz |= ew[i];
        if (nz) odd_nonzero = 1;
        __syncthreads();
        const bool is64 = (odd_nonzero == 0);
        for (int e = t; e < NE; e += 256) {
            int s, d;
            if (is64) { s = ew[2 * e]; d = ew[2 * (NE + e)]; }
            else      { s = ew[e];     d = ew[NE + e]; }
            src_sh[e] = (unsigned char)(s & 127);
            dst_sh[e] = (unsigned char)(d & 127);
        }
        __syncthreads();
        for (int e = t; e < NE; e += 256) atomicAdd(&cnt[dst_sh[e]], 1);
        __syncthreads();
        // degree rank (ascending, stable)
        if (t < NUMK) {
            int c = cnt[t], r = 0;
            for (int m = 0; m < NUMK; m++) {
                int cm = cnt[m];
                r += (cm < c) || (cm == c && m < t);
            }
            rank_sh[t] = r;
            g_rank[t]  = r;
            cntr[r]    = c;
        }
        __syncthreads();
        // exclusive prefix over %4-PADDED rank-space counts
        if (t < NUMK) {
            int lane = t & 31, w = t >> 5;
            int v = (cntr[t] + 3) & ~3;          // pad to multiple of 4
            int sc = v;
            #pragma unroll
            for (int o = 1; o < 32; o <<= 1) {
                int u = __shfl_up_sync(0xffffffffu, sc, o);
                if (lane >= o) sc += u;
            }
            if (lane == 31) wsum[w] = sc;
            __syncwarp();
        }
        __syncthreads();
        if (t < NUMK) {
            int lane = t & 31, w = t >> 5;
            int off = 0;
            for (int i = 0; i < w; i++) off += wsum[i];
            int v = (cntr[t] + 3) & ~3;
            int sc = v;
            #pragma unroll
            for (int o = 1; o < 32; o <<= 1) {
                int u = __shfl_up_sync(0xffffffffu, sc, o);
                if (lane >= o) sc += u;
            }
            base_sh[t] = off + sc - v;
            g_ptr[t] = off + sc - v;
            if (t == 127) g_ptr[NUMK] = off + sc;
            cnt[t] = 0;                          // reuse as fill cursor (rank space)
        }
        __syncthreads();
        for (int e = t; e < NE; e += 256) {
            int dr = rank_sh[dst_sh[e]];
            int sr = rank_sh[src_sh[e]];
            int pos = base_sh[dr] + atomicAdd(&cnt[dr], 1);
            if (pos >= NE_PAD) pos = NE_PAD - 1; // defensive
            g_einfo[e] = pos | (sr << 11) | (dr << 18);
        }
    } else {
        // ---------- piecewise-linear table row (warp 0 only) ----------
        const int j = threadIdx.x;
        if (j >= 32) return;
        __shared__ float t_sh[HD], w1_sh[HD], b1_sh[HD], tsort[HD];
        __shared__ unsigned int mask_sh;
        const int iv = blockIdx.x - 1;           // 0..32
        float w1 = W1[j], bv = b1[j];
        w1_sh[j] = w1; b1_sh[j] = bv;
        float tk = (w1 == 0.f) ? CUDART_INF_F : (-bv / w1);
        t_sh[j] = tk;
        if (iv == 0) g_t[j] = tk;
        __syncwarp();
        int r = 0;
        #pragma unroll
        for (int m = 0; m < HD; m++) {
            float tm = t_sh[m];
            r += (tm < tk) || (tm == tk && m < j);
        }
        tsort[r] = tk;
        __syncwarp();
        if (j == 0) {
            float s;
            if (iv == 0)       s = tsort[0] - fabsf(tsort[0]) - 1.f;
            else if (iv == 32) s = tsort[31] + fabsf(tsort[31]) + 1.f;
            else               s = 0.5f * (tsort[iv - 1] + tsort[iv]);
            unsigned m = 0;
            for (int k = 0; k < HD; k++) {
                float w = w1_sh[k], tt = t_sh[k];
                bool act = (w > 0.f) ? (s > tt)
                         : (w < 0.f) ? (s < tt)
                                     : (b1_sh[k] > 0.f);
                if (act) m |= 1u << k;
            }
            mask_sh = m;
        }
        __syncwarp();
        const unsigned m = mask_sh;
        float accA = 0.f, accC = 0.f;
        #pragma unroll
        for (int k = 0; k < HD; k++) {
            if ((m >> k) & 1u) {
                float w2 = __ldg(&W2[k * HD + j]);
                accA = fmaf(w1_sh[k], w2, accA);
                accC = fmaf(b1_sh[k], w2, accC);
            }
        }
        g_A[iv * HD + j] = accA;
        g_C[iv * HD + j] = accC;
    }
}

// One CTA per graph, 256 threads, degree-rank space.
// h stored fp16; pass-D edge accumulation in packed HFMA2 (fp16), epilogue fp32.
// ns packed: half(w)<<16 | src_rank*64 (byte off). CSR segments %4 -> uint4 streams.
__global__ __launch_bounds__(256, 7) void gcn_main(
    const float* __restrict__ Hx,
    const float* __restrict__ b2,
    const float* __restrict__ W3,
    const float* __restrict__ b3,
    float* __restrict__ out)
{
    __shared__ float  p_s[NUMK];                 // p (rank space), then p' = dinv*p
    __shared__ int    ptr_s[NUMK + 1];
    __shared__ int    rank_s[NUMK];
    __shared__ float  dinv_s[NUMK];
    __shared__ float2 sc_s[NUMK];                // (s1_final, dinv)
    __shared__ float  h3_s[NUMK];                // t' (pre-scaled layer-2 out scalar)
    __shared__ float  res_s[NUMK];               // final per-rank result
    __shared__ __align__(16) unsigned int ns_s[NE_PAD]; // half(w)<<16 | src_rank*64
    __shared__ __align__(16) unsigned int h2_s[NUMK * 16]; // fp16 h, 64B/row
    __shared__ __align__(16) float b2_s[HD], W3_s[HD];

    const int g    = blockIdx.x;
    const int tid  = threadIdx.x;
    const int lane = tid & 31;
    const int warp = tid >> 5;
    const int node = tid >> 1;                   // rank, 2 threads per node
    const int par  = tid & 1;
    const float* row = Hx + (long long)g * ROWLEN;

    // ---- stage + zero-fill ns (pad slots must read as w=0) ----
    if (tid < NUMK) {
        int rk = __ldg(&g_rank[tid]);
        rank_s[tid] = rk;
        p_s[rk] = row[tid];                      // permute p into rank space
    }
    if (tid <= NUMK) ptr_s[tid] = g_ptr[tid];
    if (tid < HD) { b2_s[tid] = b2[tid]; W3_s[tid] = W3[tid]; }
    #pragma unroll
    for (int i = tid; i < NE_PAD / 4; i += 256)
        ((uint4*)ns_s)[i] = make_uint4(0u, 0u, 0u, 0u);
    const float tl = __ldg(&g_t[lane]);
    __syncthreads();

    // ---- pass A1: edge-parallel — coalesced w LDG, pack ns at CSR position ----
    #pragma unroll
    for (int e = tid; e < NE; e += 256) {
        float w = row[NUMK + e];                 // coalesced
        int info = __ldg(&g_einfo[e]);
        unsigned hw = (unsigned)__half_as_ushort(__float2half_rn(w));
        ns_s[info & 2047] = (hw << 16) | (unsigned)(((info >> 11) & 127) * 64);
    }
    __syncthreads();

    // ---- pass A2: 2 threads/node — degree from ns (uint4 quads, no atomics) ----
    const int begN = ptr_s[node], endN = ptr_s[node + 1];   // both %4
    {
        float deg = 0.f;
        for (int s = begN + 4 * par; s < endN; s += 8) {
            uint4 kk = *(const uint4*)&ns_s[s];
            deg += __half2float(__ushort_as_half((unsigned short)(kk.x >> 16)))
                 + __half2float(__ushort_as_half((unsigned short)(kk.y >> 16)))
                 + __half2float(__ushort_as_half((unsigned short)(kk.z >> 16)))
                 + __half2float(__ushort_as_half((unsigned short)(kk.w >> 16)));
        }
        deg += __shfl_xor_sync(0xffffffffu, deg, 1);
        deg += 1.0f;                             // self-loop
        if (par == 0) {
            float di = rsqrtf(deg);              // deg >= 1 always
            dinv_s[node] = di;
            p_s[node]   *= di;                   // p'
        }
    }
    __syncthreads();

    // ---- pass B: 2 threads/node — layer-1 scalar aggregation (uint4 quads) ----
    {
        float acc = 0.f, acc2 = 0.f;
        for (int s = begN + 4 * par; s < endN; s += 8) {
            uint4 kk = *(const uint4*)&ns_s[s];
            float w0 = __half2float(__ushort_as_half((unsigned short)(kk.x >> 16)));
            float w1 = __half2float(__ushort_as_half((unsigned short)(kk.y >> 16)));
            float w2 = __half2float(__ushort_as_half((unsigned short)(kk.z >> 16)));
            float w3 = __half2float(__ushort_as_half((unsigned short)(kk.w >> 16)));
            acc  = fmaf(w0, p_s[(kk.x & 0xffffu) >> 6], acc);
            acc2 = fmaf(w1, p_s[(kk.y & 0xffffu) >> 6], acc2);
            acc  = fmaf(w2, p_s[(kk.z & 0xffffu) >> 6], acc);
            acc2 = fmaf(w3, p_s[(kk.w & 0xffffu) >> 6], acc2);
        }
        acc += acc2;
        acc += __shfl_xor_sync(0xffffffffu, acc, 1);
        if (par == 0) {
            float di = dinv_s[node];
            sc_s[node] = make_float2(di * (acc + p_s[node]), di);
        }
    }
    __syncthreads();

    // ---- pass C: h' = dinv*(s1*A[iv] + C[iv]); store fp16 ----
    {
        __half* hh = (__half*)h2_s;
        #pragma unroll
        for (int i = 0; i < 16; i++) {
            const int n = (warp << 4) + i;
            float2 sc = sc_s[n];
            unsigned bl = __ballot_sync(0xffffffffu, tl < sc.x);
            int iv = __popc(bl);
            float v = sc.y * fmaf(sc.x, __ldg(&g_A[iv * HD + lane]),
                                        __ldg(&g_C[iv * HD + lane]));
            hh[n * HD + lane] = __float2half_rn(v);
        }
    }
    __syncthreads();

    // ---- pass D: layer-2 aggregation, HFMA2, 4 edges/iter via uint4 ns ----
    {
        const int li  = lane & 7;
        const int sub = lane >> 3;
        const float4 b24 = *(const float4*)&b2_s[li * 4];
        const float4 w34 = *(const float4*)&W3_s[li * 4];
        const char* hbase = (const char*)h2_s + 8 * li;  // per-lane byte base
        #pragma unroll
        for (int ps = 0; ps < 4; ps++) {
            const int q = ps * 8 + warp;         // stripe groups across warps
            const int n = q * 4 + sub;           // 4 consecutive ranks per group
            const float di = sc_s[n].y;
            // self term: h' row read directly as half2 pairs (no conversion)
            uint2 su = *(const uint2*)(hbase + n * 64);
            __half2 accA = *(const __half2*)&su.x;   // cols 0-1
            __half2 accB = *(const __half2*)&su.y;   // cols 2-3
            __half2 accC = __float2half2_rn(0.f);
            __half2 accD = __float2half2_rn(0.f);
            const int beg = ptr_s[n], end = ptr_s[n + 1];   // %4, %4
            for (int s = beg; s < end; s += 4) {
                uint4 kk = *(const uint4*)&ns_s[s];
                unsigned w0d, w1d, w2d, w3d;
                asm("prmt.b32 %0, %1, %1, 0x3232;" : "=r"(w0d) : "r"(kk.x));
                asm("prmt.b32 %0, %1, %1, 0x3232;" : "=r"(w1d) : "r"(kk.y));
                asm("prmt.b32 %0, %1, %1, 0x3232;" : "=r"(w2d) : "r"(kk.z));
                asm("prmt.b32 %0, %1, %1, 0x3232;" : "=r"(w3d) : "r"(kk.w));
                uint2 u0 = *(const uint2*)(hbase + (kk.x & 0xffffu));
                uint2 u1 = *(const uint2*)(hbase + (kk.y & 0xffffu));
                uint2 u2 = *(const uint2*)(hbase + (kk.z & 0xffffu));
                uint2 u3 = *(const uint2*)(hbase + (kk.w & 0xffffu));
                accA = __hfma2(*(const __half2*)&w0d, *(const __half2*)&u0.x, accA);
                accB = __hfma2(*(const __half2*)&w0d, *(const __half2*)&u0.y, accB);
                accC = __hfma2(*(const __half2*)&w1d, *(const __half2*)&u1.x, accC);
                accD = __hfma2(*(const __half2*)&w1d, *(const __half2*)&u1.y, accD);
                accA = __hfma2(*(const __half2*)&w2d, *(const __half2*)&u2.x, accA);
                accB = __hfma2(*(const __half2*)&w2d, *(const __half2*)&u2.y, accB);
                accC = __hfma2(*(const __half2*)&w3d, *(const __half2*)&u3.x, accC);
                accD = __hfma2(*(const __half2*)&w3d, *(const __half2*)&u3.y, accD);
            }
            accA = __hadd2(accA, accC);
            accB = __hadd2(accB, accD);
            float2 fa = __half22float2(accA);
            float2 fb = __half22float2(accB);
            float v = fmaxf(fmaf(di, fa.x, b24.x), 0.f) * w34.x
                    + fmaxf(fmaf(di, fa.y, b24.y), 0.f) * w34.y
                    + fmaxf(fmaf(di, fb.x, b24.z), 0.f) * w34.z
                    + fmaxf(fmaf(di, fb.y, b24.w), 0.f) * w34.w;
            v += __shfl_xor_sync(0xffffffffu, v, 4);
            v += __shfl_xor_sync(0xffffffffu, v, 2);
            v += __shfl_xor_sync(0xffffffffu, v, 1);
            if (li == 0) h3_s[n] = di * v;       // pre-scaled t'
        }
    }
    __syncthreads();

    // ---- pass E: 2 threads/node — layer-3 scalar aggregation (uint4 quads) ----
    {
        float acc = 0.f, acc2 = 0.f;
        for (int s = begN + 4 * par; s < endN; s += 8) {
            uint4 kk = *(const uint4*)&ns_s[s];
            float w0 = __half2float(__ushort_as_half((unsigned short)(kk.x >> 16)));
            float w1 = __half2float(__ushort_as_half((unsigned short)(kk.y >> 16)));
            float w2 = __half2float(__ushort_as_half((unsigned short)(kk.z >> 16)));
            float w3 = __half2float(__ushort_as_half((unsigned short)(kk.w >> 16)));
            acc  = fmaf(w0, h3_s[(kk.x & 0xffffu) >> 6], acc);
            acc2 = fmaf(w1, h3_s[(kk.y & 0xffffu) >> 6], acc2);
            acc  = fmaf(w2, h3_s[(kk.z & 0xffffu) >> 6], acc);
            acc2 = fmaf(w3, h3_s[(kk.w & 0xffffu) >> 6], acc2);
        }
        acc += acc2;
        acc += __shfl_xor_sync(0xffffffffu, acc, 1);
        if (par == 0)
            res_s[node] = fmaf(dinv_s[node], acc + h3_s[node], __ldg(&b3[0]));
    }
    __syncthreads();

    // ---- output: remap rank -> original node order, coalesced store ----
    if (tid < NUMK)
        out[(long long)g * NUMK + tid] = res_s[rank_s[tid]];
}

extern "C" void kernel_launch(void* const* d_in, const int* in_sizes, int n_in,
                              void* d_out, int out_size) {
    const float* Hx = (const float*)d_in[0];
    const int*   ei = (const int*)d_in[1];
    const float* W1 = (const float*)d_in[2];
    const float* b1 = (const float*)d_in[3];
    const float* W2 = (const float*)d_in[4];
    const float* b2 = (const float*)d_in[5];
    const float* W3 = (const float*)d_in[6];
    const float* b3 = (const float*)d_in[7];
    float* out = (float*)d_out;

    gcn_prep<<<34, 256>>>(ei, W1, b1, W2);
    gcn_main<<<NGRAPHS, 256>>>(Hx, b2, W3, b3, out);
}

// round 15
// speedup vs baseline: 1.0369x; 1.0369x over previous
#include <cuda_runtime.h>
#include <cuda_fp16.h>
#include <math_constants.h>

#define NGRAPHS 2048
#define NUMK    128
#define NE      1024
#define NE_PAD  1152            // NE + up to 1 pad slot per node (even segments)
#define HD      32
#define ROWLEN  (NUMK + NE + 2)

// Built once per launch (edge template + weights identical across graphs).
// All node ids below are DEGREE-SORTED RANKS. CSR segments padded to even length.
__device__ __align__(16) int g_einfo[NE];       // per edge id: csr_pos | src_rank<<11 | dst_rank<<18
__device__ int g_ptr[NUMK + 1];                 // padded CSR ptr over dst ranks (all even)
__device__ int g_rank[NUMK];                    // original node -> rank
__device__ float g_t[HD];                       // relu thresholds t_k = -b1k/W1k
__device__ __align__(16) float g_A[33 * HD];    // h = s1*A[iv] + C[iv]
__device__ __align__(16) float g_C[33 * HD];

// ---- single prep launch: block 0 = rank+CSR build; blocks 1..33 = tables ----
__global__ __launch_bounds__(256) void gcn_prep(const int* __restrict__ ew,
                                                const float* __restrict__ W1,
                                                const float* __restrict__ b1,
                                                const float* __restrict__ W2) {
    if (blockIdx.x == 0) {
        __shared__ unsigned char src_sh[NE], dst_sh[NE];
        __shared__ int cnt[NUMK];
        __shared__ int rank_sh[NUMK];
        __shared__ int cntr[NUMK];
        __shared__ int base_sh[NUMK + 1];
        __shared__ int wsum[4];
        __shared__ int odd_nonzero;
        const int t = threadIdx.x;
        if (t == 0) odd_nonzero = 0;
        if (t < NUMK) cnt[t] = 0;
        __syncthreads();
        // int32 vs int64 layout guard: odd words all-zero => little-endian int64
        int nz = 0;
        for (int i = t * 2 + 1; i < 2 * NE; i += 512) nz |= ew[i];
        if (nz) odd_nonzero = 1;
        __syncthreads();
        const bool is64 = (odd_nonzero == 0);
        for (int e = t; e < NE; e += 256) {
            int s, d;
            if (is64) { s = ew[2 * e]; d = ew[2 * (NE + e)]; }
            else      { s = ew[e];     d = ew[NE + e]; }
            src_sh[e] = (unsigned char)(s & 127);
            dst_sh[e] = (unsigned char)(d & 127);
        }
        __syncthreads();
        for (int e = t; e < NE; e += 256) atomicAdd(&cnt[dst_sh[e]], 1);
        __syncthreads();
        // degree rank (ascending, stable)
        if (t < NUMK) {
            int c = cnt[t], r = 0;
            for (int m = 0; m < NUMK; m++) {
                int cm = cnt[m];
                r += (cm < c) || (cm == c && m < t);
            }
            rank_sh[t] = r;
            g_rank[t]  = r;
            cntr[r]    = c;
        }
        __syncthreads();
        // exclusive prefix over EVEN-PADDED rank-space counts
        if (t < NUMK) {
            int lane = t & 31, w = t >> 5;
            int v = (cntr[t] + 1) & ~1;          // pad to even
            int sc = v;
            #pragma unroll
            for (int o = 1; o < 32; o <<= 1) {
                int u = __shfl_up_sync(0xffffffffu, sc, o);
                if (lane >= o) sc += u;
            }
            if (lane == 31) wsum[w] = sc;
            __syncwarp();
        }
        __syncthreads();
        if (t < NUMK) {
            int lane = t & 31, w = t >> 5;
            int off = 0;
            for (int i = 0; i < w; i++) off += wsum[i];
            int v = (cntr[t] + 1) & ~1;
            int sc = v;
            #pragma unroll
            for (int o = 1; o < 32; o <<= 1) {
                int u = __shfl_up_sync(0xffffffffu, sc, o);
                if (lane >= o) sc += u;
            }
            base_sh[t] = off + sc - v;
            g_ptr[t] = off + sc - v;
            if (t == 127) g_ptr[NUMK] = off + sc;
            cnt[t] = 0;                          // reuse as fill cursor (rank space)
        }
        __syncthreads();
        for (int e = t; e < NE; e += 256) {
            int dr = rank_sh[dst_sh[e]];
            int sr = rank_sh[src_sh[e]];
            int pos = base_sh[dr] + atomicAdd(&cnt[dr], 1);
            if (pos >= NE_PAD) pos = NE_PAD - 1; // defensive
            g_einfo[e] = pos | (sr << 11) | (dr << 18);
        }
    } else {
        // ---------- piecewise-linear table row (warp 0 only) ----------
        const int j = threadIdx.x;
        if (j >= 32) return;
        __shared__ float t_sh[HD], w1_sh[HD], b1_sh[HD], tsort[HD];
        __shared__ unsigned int mask_sh;
        const int iv = blockIdx.x - 1;           // 0..32
        float w1 = W1[j], bv = b1[j];
        w1_sh[j] = w1; b1_sh[j] = bv;
        float tk = (w1 == 0.f) ? CUDART_INF_F : (-bv / w1);
        t_sh[j] = tk;
        if (iv == 0) g_t[j] = tk;
        __syncwarp();
        int r = 0;
        #pragma unroll
        for (int m = 0; m < HD; m++) {
            float tm = t_sh[m];
            r += (tm < tk) || (tm == tk && m < j);
        }
        tsort[r] = tk;
        __syncwarp();
        if (j == 0) {
            float s;
            if (iv == 0)       s = tsort[0] - fabsf(tsort[0]) - 1.f;
            else if (iv == 32) s = tsort[31] + fabsf(tsort[31]) + 1.f;
            else               s = 0.5f * (tsort[iv - 1] + tsort[iv]);
            unsigned m = 0;
            for (int k = 0; k < HD; k++) {
                float w = w1_sh[k], tt = t_sh[k];
                bool act = (w > 0.f) ? (s > tt)
                         : (w < 0.f) ? (s < tt)
                                     : (b1_sh[k] > 0.f);
                if (act) m |= 1u << k;
            }
            mask_sh = m;
        }
        __syncwarp();
        const unsigned m = mask_sh;
        float accA = 0.f, accC = 0.f;
        #pragma unroll
        for (int k = 0; k < HD; k++) {
            if ((m >> k) & 1u) {
                float w2 = __ldg(&W2[k * HD + j]);
                accA = fmaf(w1_sh[k], w2, accA);
                accC = fmaf(b1_sh[k], w2, accC);
            }
        }
        g_A[iv * HD + j] = accA;
        g_C[iv * HD + j] = accC;
    }
}

// One CTA per graph, 256 threads, degree-rank space.
// h stored fp16; pass-D edge accumulation in packed HFMA2 (fp16), epilogue fp32.
// ns packed: half(w)<<16 | src_rank*64 (byte off). CSR segments even-length.
__global__ __launch_bounds__(256, 7) void gcn_main(
    const float* __restrict__ Hx,
    const float* __restrict__ b2,
    const float* __restrict__ W3,
    const float* __restrict__ b3,
    float* __restrict__ out)
{
    __shared__ float  p_s[NUMK];                 // p (rank space), then p' = dinv*p
    __shared__ int    ptr_s[NUMK + 1];
    __shared__ int    rank_s[NUMK];
    __shared__ float  dinv_s[NUMK];
    __shared__ float2 sc_s[NUMK];                // (s1_final, dinv)
    __shared__ float  h3_s[NUMK];                // t' (pre-scaled layer-2 out scalar)
    __shared__ float  res_s[NUMK];               // final per-rank result
    __shared__ __align__(16) unsigned int ns_s[NE_PAD]; // half(w)<<16 | src_rank*64
    __shared__ __align__(16) unsigned int h2_s[NUMK * 16]; // fp16 h, 64B/row
    __shared__ __align__(16) float b2_s[HD], W3_s[HD];

    const int g    = blockIdx.x;
    const int tid  = threadIdx.x;
    const int lane = tid & 31;
    const int warp = tid >> 5;
    const int node = tid >> 1;                   // rank, 2 threads per node
    const int par  = tid & 1;
    const float* row = Hx + (long long)g * ROWLEN;

    // ---- stage + zero-fill ns (pad slots must read as w=0) ----
    if (tid < NUMK) {
        int rk = __ldg(&g_rank[tid]);
        rank_s[tid] = rk;
        p_s[rk] = row[tid];                      // permute p into rank space
    }
    if (tid <= NUMK) ptr_s[tid] = g_ptr[tid];
    if (tid < HD) { b2_s[tid] = b2[tid]; W3_s[tid] = W3[tid]; }
    #pragma unroll
    for (int i = tid; i < NE_PAD / 4; i += 256)
        ((uint4*)ns_s)[i] = make_uint4(0u, 0u, 0u, 0u);
    const float tl = __ldg(&g_t[lane]);
    __syncthreads();

    // ---- pass A1: edge-parallel — 4 edges/thread, vectorized LDG ----
    {
        const float2* rp2 = (const float2*)row;
        float2 w01 = rp2[64 + 2 * tid];          // w[4tid], w[4tid+1]
        float2 w23 = rp2[64 + 2 * tid + 1];      // w[4tid+2], w[4tid+3]
        int4 ii = ((const int4*)g_einfo)[tid];   // einfo[4tid .. 4tid+3]
        unsigned h0 = (unsigned)__half_as_ushort(__float2half_rn(w01.x));
        unsigned h1 = (unsigned)__half_as_ushort(__float2half_rn(w01.y));
        unsigned h2 = (unsigned)__half_as_ushort(__float2half_rn(w23.x));
        unsigned h3 = (unsigned)__half_as_ushort(__float2half_rn(w23.y));
        ns_s[ii.x & 2047] = (h0 << 16) | (unsigned)(((ii.x >> 11) & 127) * 64);
        ns_s[ii.y & 2047] = (h1 << 16) | (unsigned)(((ii.y >> 11) & 127) * 64);
        ns_s[ii.z & 2047] = (h2 << 16) | (unsigned)(((ii.z >> 11) & 127) * 64);
        ns_s[ii.w & 2047] = (h3 << 16) | (unsigned)(((ii.w >> 11) & 127) * 64);
    }
    __syncthreads();

    // ---- pass A2: 2 threads/node — degree from ns (uint2 pairs, no atomics) ----
    const int begN = ptr_s[node], endN = ptr_s[node + 1];   // both even
    {
        float deg = 0.f;
        for (int s = begN + 2 * par; s < endN; s += 4) {
            uint2 kk = *(const uint2*)&ns_s[s];
            deg += __half2float(__ushort_as_half((unsigned short)(kk.x >> 16)))
                 + __half2float(__ushort_as_half((unsigned short)(kk.y >> 16)));
        }
        deg += __shfl_xor_sync(0xffffffffu, deg, 1);
        deg += 1.0f;                             // self-loop
        if (par == 0) {
            float di = rsqrtf(deg);              // deg >= 1 always
            dinv_s[node] = di;
            p_s[node]   *= di;                   // p'
        }
    }
    __syncthreads();

    // ---- pass B: 2 threads/node — layer-1 scalar aggregation (uint2 pairs) ----
    {
        float acc = 0.f, acc2 = 0.f;
        for (int s = begN + 2 * par; s < endN; s += 4) {
            uint2 kk = *(const uint2*)&ns_s[s];
            float w0 = __half2float(__ushort_as_half((unsigned short)(kk.x >> 16)));
            float w1 = __half2float(__ushort_as_half((unsigned short)(kk.y >> 16)));
            acc  = fmaf(w0, p_s[(kk.x & 0xffffu) >> 6], acc);
            acc2 = fmaf(w1, p_s[(kk.y & 0xffffu) >> 6], acc2);
        }
        acc += acc2;
        acc += __shfl_xor_sync(0xffffffffu, acc, 1);
        if (par == 0) {
            float di = dinv_s[node];
            sc_s[node] = make_float2(di * (acc + p_s[node]), di);
        }
    }
    __syncthreads();

    // ---- pass C: h' = dinv*(s1*A[iv] + C[iv]); store fp16 ----
    {
        __half* hh = (__half*)h2_s;
        #pragma unroll
        for (int i = 0; i < 16; i++) {
            const int n = (warp << 4) + i;
            float2 sc = sc_s[n];
            unsigned bl = __ballot_sync(0xffffffffu, tl < sc.x);
            int iv = __popc(bl);
            float v = sc.y * fmaf(sc.x, __ldg(&g_A[iv * HD + lane]),
                                        __ldg(&g_C[iv * HD + lane]));
            hh[n * HD + lane] = __float2half_rn(v);
        }
    }
    __syncthreads();

    // ---- pass D: layer-2 aggregation, HFMA2 packed fp16, fp32 epilogue ----
    {
        const int li  = lane & 7;
        const int sub = lane >> 3;
        const float4 b24 = *(const float4*)&b2_s[li * 4];
        const float4 w34 = *(const float4*)&W3_s[li * 4];
        const char* hbase = (const char*)h2_s + 8 * li;  // per-lane byte base
        #pragma unroll
        for (int ps = 0; ps < 4; ps++) {
            const int q = ps * 8 + warp;         // stripe groups across warps
            const int n = q * 4 + sub;           // 4 consecutive ranks per group
            const float di = sc_s[n].y;
            // self term: h' row read directly as half2 pairs (no conversion)
            uint2 su = *(const uint2*)(hbase + n * 64);
            __half2 accA = *(const __half2*)&su.x;   // cols 0-1
            __half2 accB = *(const __half2*)&su.y;   // cols 2-3
            __half2 accC = __float2half2_rn(0.f);
            __half2 accD = __float2half2_rn(0.f);
            const int beg = ptr_s[n], end = ptr_s[n + 1];   // even, even
            for (int s = beg; s < end; s += 2) {
                uint2 kk = *(const uint2*)&ns_s[s];
                unsigned w0d, w1d;
                asm("prmt.b32 %0, %1, %1, 0x3232;" : "=r"(w0d) : "r"(kk.x));
                asm("prmt.b32 %0, %1, %1, 0x3232;" : "=r"(w1d) : "r"(kk.y));
                uint2 u0 = *(const uint2*)(hbase + (kk.x & 0xffffu));
                uint2 u1 = *(const uint2*)(hbase + (kk.y & 0xffffu));
                accA = __hfma2(*(const __half2*)&w0d, *(const __half2*)&u0.x, accA);
                accB = __hfma2(*(const __half2*)&w0d, *(const __half2*)&u0.y, accB);
                accC = __hfma2(*(const __half2*)&w1d, *(const __half2*)&u1.x, accC);
                accD = __hfma2(*(const __half2*)&w1d, *(const __half2*)&u1.y, accD);
            }
            accA = __hadd2(accA, accC);
            accB = __hadd2(accB, accD);
            float2 fa = __half22float2(accA);
            float2 fb = __half22float2(accB);
            float v = fmaxf(fmaf(di, fa.x, b24.x), 0.f) * w34.x
                    + fmaxf(fmaf(di, fa.y, b24.y), 0.f) * w34.y
                    + fmaxf(fmaf(di, fb.x, b24.z), 0.f) * w34.z
                    + fmaxf(fmaf(di, fb.y, b24.w), 0.f) * w34.w;
            v += __shfl_xor_sync(0xffffffffu, v, 4);
            v += __shfl_xor_sync(0xffffffffu, v, 2);
            v += __shfl_xor_sync(0xffffffffu, v, 1);
            if (li == 0) h3_s[n] = di * v;       // pre-scaled t'
        }
    }
    __syncthreads();

    // ---- pass E: 2 threads/node — layer-3 scalar aggregation (uint2 pairs) ----
    {
        float acc = 0.f, acc2 = 0.f;
        for (int s = begN + 2 * par; s < endN; s += 4) {
            uint2 kk = *(const uint2*)&ns_s[s];
            float w0 = __half2float(__ushort_as_half((unsigned short)(kk.x >> 16)));
            float w1 = __half2float(__ushort_as_half((unsigned short)(kk.y >> 16)));
            acc  = fmaf(w0, h3_s[(kk.x & 0xffffu) >> 6], acc);
            acc2 = fmaf(w1, h3_s[(kk.y & 0xffffu) >> 6], acc2);
        }
        acc += acc2;
        acc += __shfl_xor_sync(0xffffffffu, acc, 1);
        if (par == 0)
            res_s[node] = fmaf(dinv_s[node], acc + h3_s[node], __ldg(&b3[0]));
    }
    __syncthreads();

    // ---- output: remap rank -> original node order, coalesced store ----
    if (tid < NUMK)
        out[(long long)g * NUMK + tid] = res_s[rank_s[tid]];
}

extern "C" void kernel_launch(void* const* d_in, const int* in_sizes, int n_in,
                              void* d_out, int out_size) {
    const float* Hx = (const float*)d_in[0];
    const int*   ei = (const int*)d_in[1];
    const float* W1 = (const float*)d_in[2];
    const float* b1 = (const float*)d_in[3];
    const float* W2 = (const float*)d_in[4];
    const float* b2 = (const float*)d_in[5];
    const float* W3 = (const float*)d_in[6];
    const float* b3 = (const float*)d_in[7];
    float* out = (float*)d_out;

    gcn_prep<<<34, 256>>>(ei, W1, b1, W2);
    gcn_main<<<NGRAPHS, 256>>>(Hx, b2, W3, b3, out);
}